// round 2
// baseline (speedup 1.0000x reference)
#include <cuda_runtime.h>
#include <cstdint>

// Problem constants (fixed by the reference)
#define N_NODES   100000
#define FDIM      512
#define EDIM      256
#define NB        16384      // batch
#define S_SAMP    10

__device__ float g_agg[(size_t)NB * FDIM];   // 32 MB scratch for aggregated features
__device__ int   g_idx64;                    // 1 if neigh_idx is int64, 0 if int32

// --------------------------------------------------------------------------
// Detect index dtype: interpret the first 10 logical indices as int64. If all
// are in [0, N_NODES) the buffer is int64 (high words zero); random int32
// payload in the odd words makes that essentially impossible otherwise.
// Reads only the first 20 int32 words — in-bounds under both layouts.
// --------------------------------------------------------------------------
__global__ void k_detect(const int* __restrict__ w) {
    if (threadIdx.x == 0) {
        int ok = 1;
#pragma unroll
        for (int s = 0; s < S_SAMP; s++) {
            long long v = (long long)(unsigned)w[2 * s] | ((long long)w[2 * s + 1] << 32);
            if (v < 0 || v >= N_NODES) ok = 0;
        }
        g_idx64 = ok;
    }
}

// --------------------------------------------------------------------------
// Gather + mean. 4 batch rows per block (threadIdx.y), 128 threads per row:
// each thread owns one float4 column slice (512 floats / row). The 10
// independent 2KB row fetches per batch row give high MLP; DRAM-bound.
// --------------------------------------------------------------------------
#define GROWS 4
__global__ __launch_bounds__(512) void k_gather(const float* __restrict__ feat,
                                                const int* __restrict__ idxw) {
    int b = blockIdx.x * GROWS + threadIdx.y;
    int t = threadIdx.x;          // 0..127
    int lane = t & 31;
    int is64 = g_idx64;

    int myid = 0;
    if (lane < S_SAMP) {
        int p = b * S_SAMP + lane;
        myid = is64 ? idxw[2 * p] : idxw[p];   // low word carries the value
    }

    float4 acc = make_float4(0.f, 0.f, 0.f, 0.f);
#pragma unroll
    for (int s = 0; s < S_SAMP; s++) {
        int id = __shfl_sync(0xffffffffu, myid, s);
        float4 v = *(const float4*)(feat + (size_t)id * FDIM + t * 4);
        acc.x += v.x; acc.y += v.y; acc.z += v.z; acc.w += v.w;
    }
    const float inv = 1.0f / (float)S_SAMP;
    acc.x *= inv; acc.y *= inv; acc.z *= inv; acc.w *= inv;
    *(float4*)(g_agg + (size_t)b * FDIM + t * 4) = acc;
}

// --------------------------------------------------------------------------
// SGEMM-NT + leaky ReLU epilogue.
// C[e, b] = sum_k W[e, k] * agg[b, k];  out = y >= 0 ? y : y * 11/48
// Tile: BM=128 (E), BN=128 (B), BK=16; 256 threads, 8x8 micro-tile.
// --------------------------------------------------------------------------
#define BM 128
#define BN 128
#define BK 16

__global__ __launch_bounds__(256) void k_gemm(const float* __restrict__ Wt,
                                              float* __restrict__ out) {
    __shared__ float As[BK][BM];   // W tile, k-major (transposed on store)
    __shared__ float Bs[BK][BN];   // agg tile, k-major

    const float* Ag = g_agg;
    const float SLOPE = 11.0f / 48.0f;

    int tid = threadIdx.x;
    int n0 = blockIdx.x * BN;
    int m0 = blockIdx.y * BM;
    int tc = tid & 15;       // 0..15 -> column group (B)
    int tr = tid >> 4;       // 0..15 -> row group (E)
    int lrow = tid >> 2;     // 0..63 : global-load row within tile
    int lc = (tid & 3) * 4;  // 0,4,8,12 : float4 offset within BK

    float acc[8][8];
#pragma unroll
    for (int i = 0; i < 8; i++)
#pragma unroll
        for (int j = 0; j < 8; j++) acc[i][j] = 0.f;

    for (int k0 = 0; k0 < FDIM; k0 += BK) {
        // Global loads issued before the barrier to overlap latency
        float4 w0 = *(const float4*)(Wt + (size_t)(m0 + lrow) * FDIM + k0 + lc);
        float4 w1 = *(const float4*)(Wt + (size_t)(m0 + lrow + 64) * FDIM + k0 + lc);
        float4 a0 = *(const float4*)(Ag + (size_t)(n0 + lrow) * FDIM + k0 + lc);
        float4 a1 = *(const float4*)(Ag + (size_t)(n0 + lrow + 64) * FDIM + k0 + lc);

        __syncthreads();   // previous iteration's reads of smem are done

        As[lc + 0][lrow] = w0.x;  As[lc + 1][lrow] = w0.y;
        As[lc + 2][lrow] = w0.z;  As[lc + 3][lrow] = w0.w;
        As[lc + 0][lrow + 64] = w1.x;  As[lc + 1][lrow + 64] = w1.y;
        As[lc + 2][lrow + 64] = w1.z;  As[lc + 3][lrow + 64] = w1.w;

        Bs[lc + 0][lrow] = a0.x;  Bs[lc + 1][lrow] = a0.y;
        Bs[lc + 2][lrow] = a0.z;  Bs[lc + 3][lrow] = a0.w;
        Bs[lc + 0][lrow + 64] = a1.x;  Bs[lc + 1][lrow + 64] = a1.y;
        Bs[lc + 2][lrow + 64] = a1.z;  Bs[lc + 3][lrow + 64] = a1.w;

        __syncthreads();

#pragma unroll
        for (int k = 0; k < BK; k++) {
            float af[8], bf[8];
            *(float4*)(af)     = *(const float4*)&As[k][tr * 8];
            *(float4*)(af + 4) = *(const float4*)&As[k][tr * 8 + 4];
            *(float4*)(bf)     = *(const float4*)&Bs[k][tc * 8];
            *(float4*)(bf + 4) = *(const float4*)&Bs[k][tc * 8 + 4];
#pragma unroll
            for (int i = 0; i < 8; i++)
#pragma unroll
                for (int j = 0; j < 8; j++)
                    acc[i][j] = fmaf(af[i], bf[j], acc[i][j]);
        }
    }

    // Epilogue: leaky ReLU + float4 stores (out is [EDIM, NB], b contiguous)
#pragma unroll
    for (int i = 0; i < 8; i++) {
        int e = m0 + tr * 8 + i;
        float* op = out + (size_t)e * NB + n0 + tc * 8;
        float r[8];
#pragma unroll
        for (int j = 0; j < 8; j++) {
            float y = acc[i][j];
            r[j] = (y >= 0.f) ? y : y * SLOPE;
        }
        *(float4*)op       = *(float4*)r;
        *(float4*)(op + 4) = *(float4*)(r + 4);
    }
}

// --------------------------------------------------------------------------
// Launch: detect dtype -> gather+mean -> GEMM+ReLU. Graph-capturable,
// allocation-free, deterministic.
// --------------------------------------------------------------------------
extern "C" void kernel_launch(void* const* d_in, const int* in_sizes, int n_in,
                              void* d_out, int out_size) {
    const float* feat = (const float*)d_in[0];
    const float* W    = (const float*)d_in[1];
    const int*   idxw = (const int*)d_in[2];   // raw int32-word view
    float* out = (float*)d_out;

    k_detect<<<1, 32>>>(idxw);
    dim3 gblk(128, GROWS);
    k_gather<<<NB / GROWS, gblk>>>(feat, idxw);
    dim3 grid(NB / BN, EDIM / BM);
    k_gemm<<<grid, 256>>>(W, out);
}

// round 4
// speedup vs baseline: 1.5610x; 1.5610x over previous
#include <cuda_runtime.h>
#include <cuda_bf16.h>
#include <cstdint>

// Problem constants (fixed by the reference)
#define N_NODES   100000
#define FDIM      512
#define EDIM      256
#define NB        16384
#define S_SAMP    10

// ---------------- device scratch (no allocations allowed) ----------------
__device__ __nv_bfloat16 g_ahi[(size_t)NB * FDIM];   // agg mean, bf16 hi
__device__ __nv_bfloat16 g_alo[(size_t)NB * FDIM];   // agg mean, bf16 lo (residual)
__device__ __nv_bfloat16 g_whi[(size_t)EDIM * FDIM]; // weight, bf16 hi
__device__ __nv_bfloat16 g_wlo[(size_t)EDIM * FDIM]; // weight, bf16 lo

static __device__ __forceinline__ uint32_t smem_u32(const void* p) {
    uint32_t a;
    asm("{ .reg .u64 t; cvta.to.shared.u64 t, %1; cvt.u32.u64 %0, t; }"
        : "=r"(a) : "l"(p));
    return a;
}

// --------------------------------------------------------------------------
// Gather + mean -> bf16 hi/lo split. 4 batch rows per block, 128 thr/row.
// Index dtype (int64 vs int32) detected per-warp from the first 10 logical
// indices (reads only the first 20 int32 words; in-bounds for both layouts).
// --------------------------------------------------------------------------
#define GROWS 4
__global__ __launch_bounds__(512) void k_gather(const float* __restrict__ feat,
                                                const int* __restrict__ idxw) {
    int b = blockIdx.x * GROWS + threadIdx.y;
    int t = threadIdx.x;          // 0..127
    int lane = t & 31;

    int is64 = 0;
    if (lane == 0) {
        int ok = 1;
#pragma unroll
        for (int s = 0; s < S_SAMP; s++) {
            long long v = (long long)(unsigned)idxw[2 * s] |
                          ((long long)idxw[2 * s + 1] << 32);
            if (v < 0 || v >= N_NODES) ok = 0;
        }
        is64 = ok;
    }
    is64 = __shfl_sync(0xffffffffu, is64, 0);

    int myid = 0;
    if (lane < S_SAMP) {
        int p = b * S_SAMP + lane;
        myid = is64 ? idxw[2 * p] : idxw[p];
    }

    float4 acc = make_float4(0.f, 0.f, 0.f, 0.f);
#pragma unroll
    for (int s = 0; s < S_SAMP; s++) {
        int id = __shfl_sync(0xffffffffu, myid, s);
        float4 v = *(const float4*)(feat + (size_t)id * FDIM + t * 4);
        acc.x += v.x; acc.y += v.y; acc.z += v.z; acc.w += v.w;
    }
    const float inv = 1.0f / (float)S_SAMP;
    float m[4] = { acc.x * inv, acc.y * inv, acc.z * inv, acc.w * inv };

    union { __nv_bfloat16 h[4]; uint2 u; } H, L;
#pragma unroll
    for (int j = 0; j < 4; j++) {
        H.h[j] = __float2bfloat16(m[j]);
        L.h[j] = __float2bfloat16(m[j] - __bfloat162float(H.h[j]));
    }
    size_t o = (size_t)b * FDIM + t * 4;
    *(uint2*)(g_ahi + o) = H.u;
    *(uint2*)(g_alo + o) = L.u;
}

// --------------------------------------------------------------------------
// Weight split: f32 -> bf16 hi/lo. 131072 elems, float4 per thread.
// --------------------------------------------------------------------------
__global__ __launch_bounds__(256) void k_wsplit(const float* __restrict__ W) {
    int i = (blockIdx.x * 256 + threadIdx.x) * 4;
    float4 w = *(const float4*)(W + i);
    float v[4] = { w.x, w.y, w.z, w.w };
    union { __nv_bfloat16 h[4]; uint2 u; } H, L;
#pragma unroll
    for (int j = 0; j < 4; j++) {
        H.h[j] = __float2bfloat16(v[j]);
        L.h[j] = __float2bfloat16(v[j] - __bfloat162float(H.h[j]));
    }
    *(uint2*)(g_whi + i) = H.u;
    *(uint2*)(g_wlo + i) = L.u;
}

// --------------------------------------------------------------------------
// bf16 split-3 GEMM via mma.sync (m16n8k16), fp32 accumulation:
//   C[e,b] = sum over virtual K' = 3*512: (Whi,Ahi), (Whi,Alo), (Wlo,Ahi)
// Block 128(E) x 128(B), 8 warps (2x4), warp tile 64x32, KC=32,
// cp.async double buffering, ldmatrix fragments, fused leaky-ReLU epilogue.
// --------------------------------------------------------------------------
#define BM 128
#define BN 128
#define KC 32
#define LDS_STRIDE 40              // bf16 elements per smem row (80B, conflict-free)
#define NCH 48                     // 3 products * (512/32)

__global__ __launch_bounds__(256, 2) void k_gemm(float* __restrict__ out) {
    __shared__ __nv_bfloat16 As[2][BM * LDS_STRIDE];
    __shared__ __nv_bfloat16 Bs[2][BN * LDS_STRIDE];

    int tid = threadIdx.x;
    int wid = tid >> 5, lane = tid & 31;
    int wm = wid >> 2;             // 0..1 -> 64-row slab (E)
    int wn = wid & 3;              // 0..3 -> 32-col slab (B)
    int m0 = blockIdx.y * BM;
    int n0 = blockIdx.x * BN;

    const __nv_bfloat16* aSrc[3] = { g_whi, g_whi, g_wlo };
    const __nv_bfloat16* bSrc[3] = { g_ahi, g_alo, g_ahi };

    // Per-thread global->shared copy slots: 512 16B vectors per tile side,
    // 2 per thread. v = tid + i*256: row = v>>2, colvec = v&3.
    int r0v = (tid + 0) >> 2, c0v = (tid + 0) & 3;
    int r1v = (tid + 256) >> 2, c1v = (tid + 256) & 3;

    uint32_t sA = smem_u32(As);
    uint32_t sB = smem_u32(Bs);
    const uint32_t bufBytesA = BM * LDS_STRIDE * 2;
    const uint32_t bufBytesB = BN * LDS_STRIDE * 2;

    float acc[4][4][4];
#pragma unroll
    for (int i = 0; i < 4; i++)
#pragma unroll
        for (int j = 0; j < 4; j++)
#pragma unroll
            for (int q = 0; q < 4; q++) acc[i][j][q] = 0.f;

    // ---- async load of one chunk into buffer `buf` ----
    auto issue = [&](int c, int buf) {
        int ph = c >> 4;
        int kc = (c & 15) * KC;
        const __nv_bfloat16* ag = aSrc[ph] + (size_t)m0 * FDIM + kc;
        const __nv_bfloat16* bg = bSrc[ph] + (size_t)n0 * FDIM + kc;
        uint32_t dA = sA + buf * bufBytesA;
        uint32_t dB = sB + buf * bufBytesB;
        asm volatile("cp.async.cg.shared.global [%0], [%1], 16;"
                     :: "r"(dA + (uint32_t)(r0v * 80 + c0v * 16)),
                        "l"(ag + (size_t)r0v * FDIM + c0v * 8));
        asm volatile("cp.async.cg.shared.global [%0], [%1], 16;"
                     :: "r"(dA + (uint32_t)(r1v * 80 + c1v * 16)),
                        "l"(ag + (size_t)r1v * FDIM + c1v * 8));
        asm volatile("cp.async.cg.shared.global [%0], [%1], 16;"
                     :: "r"(dB + (uint32_t)(r0v * 80 + c0v * 16)),
                        "l"(bg + (size_t)r0v * FDIM + c0v * 8));
        asm volatile("cp.async.cg.shared.global [%0], [%1], 16;"
                     :: "r"(dB + (uint32_t)(r1v * 80 + c1v * 16)),
                        "l"(bg + (size_t)r1v * FDIM + c1v * 8));
        asm volatile("cp.async.commit_group;");
    };

    issue(0, 0);
    issue(1, 1);

    // ldmatrix lane address components (element units)
    int aRowL = (lane & 15);
    int aColL = (lane >> 4) << 3;
    int bRowL = (lane & 7) + ((lane >> 4) << 3);
    int bColL = ((lane >> 3) & 1) << 3;

    for (int c = 0; c < NCH; c++) {
        if (c == NCH - 1) asm volatile("cp.async.wait_group 0;");
        else              asm volatile("cp.async.wait_group 1;");
        __syncthreads();

        int buf = c & 1;
        uint32_t bA = sA + buf * bufBytesA;
        uint32_t bB = sB + buf * bufBytesB;

#pragma unroll
        for (int ks = 0; ks < KC; ks += 16) {
            uint32_t aF[4][4];
            uint32_t bF[4][2];
#pragma unroll
            for (int mi = 0; mi < 4; mi++) {
                uint32_t addr = bA +
                    (uint32_t)(((wm * 64 + mi * 16 + aRowL) * LDS_STRIDE +
                                ks + aColL) * 2);
                asm volatile("ldmatrix.sync.aligned.m8n8.x4.shared.b16 "
                             "{%0,%1,%2,%3}, [%4];"
                             : "=r"(aF[mi][0]), "=r"(aF[mi][1]),
                               "=r"(aF[mi][2]), "=r"(aF[mi][3])
                             : "r"(addr));
            }
#pragma unroll
            for (int ni = 0; ni < 2; ni++) {
                uint32_t addr = bB +
                    (uint32_t)(((wn * 32 + ni * 16 + bRowL) * LDS_STRIDE +
                                ks + bColL) * 2);
                asm volatile("ldmatrix.sync.aligned.m8n8.x4.shared.b16 "
                             "{%0,%1,%2,%3}, [%4];"
                             : "=r"(bF[ni * 2][0]), "=r"(bF[ni * 2][1]),
                               "=r"(bF[ni * 2 + 1][0]), "=r"(bF[ni * 2 + 1][1])
                             : "r"(addr));
            }
#pragma unroll
            for (int mi = 0; mi < 4; mi++)
#pragma unroll
                for (int nj = 0; nj < 4; nj++) {
                    asm volatile(
                        "mma.sync.aligned.m16n8k16.row.col.f32.bf16.bf16.f32 "
                        "{%0,%1,%2,%3}, {%4,%5,%6,%7}, {%8,%9}, {%0,%1,%2,%3};"
                        : "+f"(acc[mi][nj][0]), "+f"(acc[mi][nj][1]),
                          "+f"(acc[mi][nj][2]), "+f"(acc[mi][nj][3])
                        : "r"(aF[mi][0]), "r"(aF[mi][1]),
                          "r"(aF[mi][2]), "r"(aF[mi][3]),
                          "r"(bF[nj][0]), "r"(bF[nj][1]));
                }
        }
        __syncthreads();
        if (c + 2 < NCH) issue(c + 2, buf);
    }

    // Epilogue: leaky ReLU + float2 stores. out is [EDIM][NB], b contiguous.
    const float SLOPE = 11.0f / 48.0f;
    int qrow = lane >> 2;          // 0..7
    int qcol = (lane & 3) * 2;     // 0,2,4,6
#pragma unroll
    for (int mi = 0; mi < 4; mi++) {
        int e0 = m0 + wm * 64 + mi * 16 + qrow;
#pragma unroll
        for (int nj = 0; nj < 4; nj++) {
            int b = n0 + wn * 32 + nj * 8 + qcol;
            float y0 = acc[mi][nj][0], y1 = acc[mi][nj][1];
            float y2 = acc[mi][nj][2], y3 = acc[mi][nj][3];
            float2 v0, v1;
            v0.x = (y0 >= 0.f) ? y0 : y0 * SLOPE;
            v0.y = (y1 >= 0.f) ? y1 : y1 * SLOPE;
            v1.x = (y2 >= 0.f) ? y2 : y2 * SLOPE;
            v1.y = (y3 >= 0.f) ? y3 : y3 * SLOPE;
            *(float2*)(out + (size_t)e0 * NB + b) = v0;
            *(float2*)(out + (size_t)(e0 + 8) * NB + b) = v1;
        }
    }
}

// --------------------------------------------------------------------------
// Launch: gather+split -> W split -> mma.sync GEMM. Graph-capturable,
// allocation-free, deterministic. 3 launches/call so ncu (-s 5) captures k_gemm.
// --------------------------------------------------------------------------
extern "C" void kernel_launch(void* const* d_in, const int* in_sizes, int n_in,
                              void* d_out, int out_size) {
    const float* feat = (const float*)d_in[0];
    const float* W    = (const float*)d_in[1];
    const int*   idxw = (const int*)d_in[2];
    float* out = (float*)d_out;

    dim3 gblk(128, GROWS);
    k_gather<<<NB / GROWS, gblk>>>(feat, idxw);
    k_wsplit<<<(EDIM * FDIM / 4) / 256, 256>>>(W);
    dim3 grid(NB / BN, EDIM / BM);
    k_gemm<<<grid, 256>>>(out);
}

// round 5
// speedup vs baseline: 2.0780x; 1.3312x over previous
#include <cuda_runtime.h>
#include <cuda_bf16.h>
#include <cstdint>

// Problem constants (fixed by the reference)
#define N_NODES   100000
#define FDIM      512
#define EDIM      256
#define NB        16384
#define S_SAMP    10

// ---------------- device scratch (no allocations allowed) ----------------
__device__ char  g_a1[(size_t)NB * FDIM];    // agg limb1 (int8)
__device__ char  g_a2[(size_t)NB * FDIM];    // agg limb2 (int8, /128)
__device__ char  g_w1[(size_t)EDIM * FDIM];  // weight limb1
__device__ char  g_w2[(size_t)EDIM * FDIM];  // weight limb2
__device__ float g_sa[NB];                   // per-batch-row scale
__device__ float g_sw[EDIM];                 // per-embed-row scale

static __device__ __forceinline__ uint32_t smem_u32(const void* p) {
    uint32_t a;
    asm("{ .reg .u64 t; cvta.to.shared.u64 t, %1; cvt.u32.u64 %0, t; }"
        : "=r"(a) : "l"(p));
    return a;
}
static __device__ __forceinline__ float warp_max(float v) {
#pragma unroll
    for (int o = 16; o > 0; o >>= 1)
        v = fmaxf(v, __shfl_xor_sync(0xffffffffu, v, o));
    return v;
}

// --------------------------------------------------------------------------
// Gather + mean -> per-row int8 split-2 quantization.
// 4 batch rows per block (threadIdx.y), 128 threads per row (4 floats each).
// --------------------------------------------------------------------------
#define GROWS 4
__global__ __launch_bounds__(512) void k_gather(const float* __restrict__ feat,
                                                const int* __restrict__ idxw) {
    __shared__ float smax[GROWS][4];
    int ty = threadIdx.y;
    int b = blockIdx.x * GROWS + ty;
    int t = threadIdx.x;          // 0..127
    int lane = t & 31;
    int wrp = t >> 5;

    // index dtype detect (int64 vs int32); reads first 20 words only
    int is64 = 0;
    if (lane == 0) {
        int ok = 1;
#pragma unroll
        for (int s = 0; s < S_SAMP; s++) {
            long long v = (long long)(unsigned)idxw[2 * s] |
                          ((long long)idxw[2 * s + 1] << 32);
            if (v < 0 || v >= N_NODES) ok = 0;
        }
        is64 = ok;
    }
    is64 = __shfl_sync(0xffffffffu, is64, 0);

    int myid = 0;
    if (lane < S_SAMP) {
        int p = b * S_SAMP + lane;
        myid = is64 ? idxw[2 * p] : idxw[p];
    }

    float4 acc = make_float4(0.f, 0.f, 0.f, 0.f);
#pragma unroll
    for (int s = 0; s < S_SAMP; s++) {
        int id = __shfl_sync(0xffffffffu, myid, s);
        float4 v = *(const float4*)(feat + (size_t)id * FDIM + t * 4);
        acc.x += v.x; acc.y += v.y; acc.z += v.z; acc.w += v.w;
    }
    const float inv10 = 1.0f / (float)S_SAMP;
    float m[4] = { acc.x * inv10, acc.y * inv10, acc.z * inv10, acc.w * inv10 };

    // row max reduction (abs)
    float lm = fmaxf(fmaxf(fabsf(m[0]), fabsf(m[1])),
                     fmaxf(fabsf(m[2]), fabsf(m[3])));
    lm = warp_max(lm);
    if (lane == 0) smax[ty][wrp] = lm;
    __syncthreads();
    float rmax = fmaxf(fmaxf(smax[ty][0], smax[ty][1]),
                       fmaxf(smax[ty][2], smax[ty][3]));
    rmax = fmaxf(rmax, 1e-30f);

    float qs = 127.0f / rmax;
    char4 c1, c2;
    {
        float qf, r;
        int i1, i2;
        qf = m[0] * qs; i1 = __float2int_rn(qf); r = (qf - (float)i1) * 128.f;
        i2 = __float2int_rn(r); c1.x = (char)i1; c2.x = (char)i2;
        qf = m[1] * qs; i1 = __float2int_rn(qf); r = (qf - (float)i1) * 128.f;
        i2 = __float2int_rn(r); c1.y = (char)i1; c2.y = (char)i2;
        qf = m[2] * qs; i1 = __float2int_rn(qf); r = (qf - (float)i1) * 128.f;
        i2 = __float2int_rn(r); c1.z = (char)i1; c2.z = (char)i2;
        qf = m[3] * qs; i1 = __float2int_rn(qf); r = (qf - (float)i1) * 128.f;
        i2 = __float2int_rn(r); c1.w = (char)i1; c2.w = (char)i2;
    }
    size_t o = (size_t)b * FDIM + t * 4;
    *(char4*)(g_a1 + o) = c1;
    *(char4*)(g_a2 + o) = c2;
    if (t == 0) g_sa[b] = rmax * (1.0f / 127.0f);
}

// --------------------------------------------------------------------------
// Weight quantization: one block (128 thr) per embed row.
// --------------------------------------------------------------------------
__global__ __launch_bounds__(128) void k_wq(const float* __restrict__ W) {
    __shared__ float smax[4];
    int e = blockIdx.x;
    int t = threadIdx.x;
    int lane = t & 31, wrp = t >> 5;

    float4 w = *(const float4*)(W + (size_t)e * FDIM + t * 4);
    float m[4] = { w.x, w.y, w.z, w.w };
    float lm = fmaxf(fmaxf(fabsf(m[0]), fabsf(m[1])),
                     fmaxf(fabsf(m[2]), fabsf(m[3])));
    lm = warp_max(lm);
    if (lane == 0) smax[wrp] = lm;
    __syncthreads();
    float rmax = fmaxf(fmaxf(smax[0], smax[1]), fmaxf(smax[2], smax[3]));
    rmax = fmaxf(rmax, 1e-30f);

    float qs = 127.0f / rmax;
    char4 c1, c2;
    {
        float qf, r; int i1, i2;
        qf = m[0] * qs; i1 = __float2int_rn(qf); r = (qf - (float)i1) * 128.f;
        i2 = __float2int_rn(r); c1.x = (char)i1; c2.x = (char)i2;
        qf = m[1] * qs; i1 = __float2int_rn(qf); r = (qf - (float)i1) * 128.f;
        i2 = __float2int_rn(r); c1.y = (char)i1; c2.y = (char)i2;
        qf = m[2] * qs; i1 = __float2int_rn(qf); r = (qf - (float)i1) * 128.f;
        i2 = __float2int_rn(r); c1.z = (char)i1; c2.z = (char)i2;
        qf = m[3] * qs; i1 = __float2int_rn(qf); r = (qf - (float)i1) * 128.f;
        i2 = __float2int_rn(r); c1.w = (char)i1; c2.w = (char)i2;
    }
    size_t o = (size_t)e * FDIM + t * 4;
    *(char4*)(g_w1 + o) = c1;
    *(char4*)(g_w2 + o) = c2;
    if (t == 0) g_sw[e] = rmax * (1.0f / 127.0f);
}

// --------------------------------------------------------------------------
// int8 split-2 GEMM via mma.sync m16n8k32 (s8 -> s32):
//   C[e,b] = sw[e]*sa[b] * ( accM + accX/128 )
//   accM = sum w1*a1 ; accX = sum (w1*a2 + w2*a1)
// Block 128(E) x 64(B), 8 warps (4x2), warp tile 32x32, K-chunk 64 bytes,
// cp.async double buffering, fused leaky-ReLU epilogue.
// --------------------------------------------------------------------------
#define BM 128
#define BN 64
#define KCB 64                 // bytes of K per chunk
#define NCHUNK (FDIM / KCB)    // 8
#define STRIDE 80              // padded smem row stride (bytes), conflict-free

#define OFF_W1 0
#define OFF_W2 (BM * STRIDE)               // 10240
#define OFF_A1 (2 * BM * STRIDE)           // 20480
#define OFF_A2 (2 * BM * STRIDE + BN * STRIDE)  // 25600
#define STAGE  (2 * BM * STRIDE + 2 * BN * STRIDE) // 30720
#define SMEMSZ (2 * STAGE)                 // 61440

__global__ __launch_bounds__(256, 2) void k_gemm(float* __restrict__ out) {
    extern __shared__ char sm[];
    uint32_t sb = smem_u32(sm);

    int tid = threadIdx.x;
    int wid = tid >> 5, lane = tid & 31;
    int wm = wid & 3;              // 0..3 -> 32-row slab (E)
    int wn = wid >> 2;             // 0..1 -> 32-col slab (B)
    int m0 = blockIdx.y * BM;
    int n0 = blockIdx.x * BN;

    // copy slots: A-side 512 vec (2/thread), B-side 256 vec (1/thread)
    int ar0 = (tid + 0) >> 2, ac0 = (tid + 0) & 3;
    int ar1 = (tid + 256) >> 2, ac1 = (tid + 256) & 3;
    int br = tid >> 2, bc = tid & 3;

    auto issue = [&](int c, int buf) {
        int kc = c * KCB;
        uint32_t d = sb + buf * STAGE;
        const char* w1p = g_w1 + (size_t)(m0)*FDIM + kc;
        const char* w2p = g_w2 + (size_t)(m0)*FDIM + kc;
        const char* a1p = g_a1 + (size_t)(n0)*FDIM + kc;
        const char* a2p = g_a2 + (size_t)(n0)*FDIM + kc;
        asm volatile("cp.async.cg.shared.global [%0], [%1], 16;"
                     :: "r"(d + OFF_W1 + (uint32_t)(ar0 * STRIDE + ac0 * 16)),
                        "l"(w1p + (size_t)ar0 * FDIM + ac0 * 16));
        asm volatile("cp.async.cg.shared.global [%0], [%1], 16;"
                     :: "r"(d + OFF_W1 + (uint32_t)(ar1 * STRIDE + ac1 * 16)),
                        "l"(w1p + (size_t)ar1 * FDIM + ac1 * 16));
        asm volatile("cp.async.cg.shared.global [%0], [%1], 16;"
                     :: "r"(d + OFF_W2 + (uint32_t)(ar0 * STRIDE + ac0 * 16)),
                        "l"(w2p + (size_t)ar0 * FDIM + ac0 * 16));
        asm volatile("cp.async.cg.shared.global [%0], [%1], 16;"
                     :: "r"(d + OFF_W2 + (uint32_t)(ar1 * STRIDE + ac1 * 16)),
                        "l"(w2p + (size_t)ar1 * FDIM + ac1 * 16));
        asm volatile("cp.async.cg.shared.global [%0], [%1], 16;"
                     :: "r"(d + OFF_A1 + (uint32_t)(br * STRIDE + bc * 16)),
                        "l"(a1p + (size_t)br * FDIM + bc * 16));
        asm volatile("cp.async.cg.shared.global [%0], [%1], 16;"
                     :: "r"(d + OFF_A2 + (uint32_t)(br * STRIDE + bc * 16)),
                        "l"(a2p + (size_t)br * FDIM + bc * 16));
        asm volatile("cp.async.commit_group;");
    };

    int accM[2][4][4], accX[2][4][4];
#pragma unroll
    for (int i = 0; i < 2; i++)
#pragma unroll
        for (int j = 0; j < 4; j++)
#pragma unroll
            for (int q = 0; q < 4; q++) { accM[i][j][q] = 0; accX[i][j][q] = 0; }

    issue(0, 0);
    issue(1, 1);

    // ldmatrix lane addressing (byte units)
    int aRow = lane & 15;
    int aCol = (lane >> 4) * 16;
    int bRow = (lane & 7) + ((lane >> 4) << 3);
    int bCol = ((lane >> 3) & 1) * 16;

    for (int c = 0; c < NCHUNK; c++) {
        if (c == NCHUNK - 1) asm volatile("cp.async.wait_group 0;");
        else                 asm volatile("cp.async.wait_group 1;");
        __syncthreads();

        uint32_t base = sb + (c & 1) * STAGE;
#pragma unroll
        for (int ks = 0; ks < KCB; ks += 32) {
            uint32_t w1F[2][4], w2F[2][4], b1F[4][2], b2F[4][2];
#pragma unroll
            for (int mi = 0; mi < 2; mi++) {
                uint32_t ra = (uint32_t)((wm * 32 + mi * 16 + aRow) * STRIDE +
                                         ks + aCol);
                asm volatile("ldmatrix.sync.aligned.m8n8.x4.shared.b16 "
                             "{%0,%1,%2,%3}, [%4];"
                             : "=r"(w1F[mi][0]), "=r"(w1F[mi][1]),
                               "=r"(w1F[mi][2]), "=r"(w1F[mi][3])
                             : "r"(base + OFF_W1 + ra));
                asm volatile("ldmatrix.sync.aligned.m8n8.x4.shared.b16 "
                             "{%0,%1,%2,%3}, [%4];"
                             : "=r"(w2F[mi][0]), "=r"(w2F[mi][1]),
                               "=r"(w2F[mi][2]), "=r"(w2F[mi][3])
                             : "r"(base + OFF_W2 + ra));
            }
#pragma unroll
            for (int g = 0; g < 2; g++) {
                uint32_t rb = (uint32_t)((wn * 32 + g * 16 + bRow) * STRIDE +
                                         ks + bCol);
                asm volatile("ldmatrix.sync.aligned.m8n8.x4.shared.b16 "
                             "{%0,%1,%2,%3}, [%4];"
                             : "=r"(b1F[g * 2][0]), "=r"(b1F[g * 2][1]),
                               "=r"(b1F[g * 2 + 1][0]), "=r"(b1F[g * 2 + 1][1])
                             : "r"(base + OFF_A1 + rb));
                asm volatile("ldmatrix.sync.aligned.m8n8.x4.shared.b16 "
                             "{%0,%1,%2,%3}, [%4];"
                             : "=r"(b2F[g * 2][0]), "=r"(b2F[g * 2][1]),
                               "=r"(b2F[g * 2 + 1][0]), "=r"(b2F[g * 2 + 1][1])
                             : "r"(base + OFF_A2 + rb));
            }
#pragma unroll
            for (int mi = 0; mi < 2; mi++)
#pragma unroll
                for (int nj = 0; nj < 4; nj++) {
#define IMMA(ACC, AF, BF)                                                     \
    asm volatile(                                                             \
        "mma.sync.aligned.m16n8k32.row.col.s32.s8.s8.s32 "                    \
        "{%0,%1,%2,%3}, {%4,%5,%6,%7}, {%8,%9}, {%0,%1,%2,%3};"               \
        : "+r"(ACC[mi][nj][0]), "+r"(ACC[mi][nj][1]),                          \
          "+r"(ACC[mi][nj][2]), "+r"(ACC[mi][nj][3])                           \
        : "r"(AF[mi][0]), "r"(AF[mi][1]), "r"(AF[mi][2]), "r"(AF[mi][3]),      \
          "r"(BF[nj][0]), "r"(BF[nj][1]))
                    IMMA(accM, w1F, b1F);
                    IMMA(accX, w1F, b2F);
                    IMMA(accX, w2F, b1F);
#undef IMMA
                }
        }
        __syncthreads();
        if (c + 2 < NCHUNK) issue(c + 2, c & 1);
    }

    // Epilogue: dequant + leaky ReLU + float2 stores. out is [EDIM][NB].
    const float SLOPE = 11.0f / 48.0f;
    const float INV128 = 1.0f / 128.0f;
    int qrow = lane >> 2;          // 0..7
    int qcol = (lane & 3) * 2;     // 0,2,4,6
#pragma unroll
    for (int mi = 0; mi < 2; mi++) {
        int e0 = m0 + wm * 32 + mi * 16 + qrow;
        float sw0 = g_sw[e0], sw1 = g_sw[e0 + 8];
#pragma unroll
        for (int nj = 0; nj < 4; nj++) {
            int b = n0 + wn * 32 + nj * 8 + qcol;
            float sa0 = g_sa[b], sa1 = g_sa[b + 1];
            float y0 = ((float)accM[mi][nj][0] + (float)accX[mi][nj][0] * INV128) * sw0 * sa0;
            float y1 = ((float)accM[mi][nj][1] + (float)accX[mi][nj][1] * INV128) * sw0 * sa1;
            float y2 = ((float)accM[mi][nj][2] + (float)accX[mi][nj][2] * INV128) * sw1 * sa0;
            float y3 = ((float)accM[mi][nj][3] + (float)accX[mi][nj][3] * INV128) * sw1 * sa1;
            float2 v0, v1;
            v0.x = (y0 >= 0.f) ? y0 : y0 * SLOPE;
            v0.y = (y1 >= 0.f) ? y1 : y1 * SLOPE;
            v1.x = (y2 >= 0.f) ? y2 : y2 * SLOPE;
            v1.y = (y3 >= 0.f) ? y3 : y3 * SLOPE;
            *(float2*)(out + (size_t)e0 * NB + b) = v0;
            *(float2*)(out + (size_t)(e0 + 8) * NB + b) = v1;
        }
    }
}

__global__ void k_nop() {}

// --------------------------------------------------------------------------
// Launch: gather+quant -> W quant -> IMMA GEMM -> nop (ncu alignment).
// Graph-capturable, allocation-free, deterministic.
// --------------------------------------------------------------------------
extern "C" void kernel_launch(void* const* d_in, const int* in_sizes, int n_in,
                              void* d_out, int out_size) {
    const float* feat = (const float*)d_in[0];
    const float* W    = (const float*)d_in[1];
    const int*   idxw = (const int*)d_in[2];
    float* out = (float*)d_out;

    cudaFuncSetAttribute(k_gemm, cudaFuncAttributeMaxDynamicSharedMemorySize,
                         SMEMSZ);

    dim3 gblk(128, GROWS);
    k_gather<<<NB / GROWS, gblk>>>(feat, idxw);
    k_wq<<<EDIM, 128>>>(W);
    dim3 grid(NB / BN, EDIM / BM);
    k_gemm<<<grid, 256, SMEMSZ>>>(out);
    k_nop<<<1, 32>>>();
}